// round 5
// baseline (speedup 1.0000x reference)
#include <cuda_runtime.h>

// ---------------------------------------------------------------------------
// BackwardConv2D: out = conv_transpose adjoint == forward SAME 3x3 conv with
// flipped kernel and Cin/Cout swapped, over 512 images (2 tensors x B=8 x N=32)
// of 32x32x64 fp32. lane == n (innermost dim of both input and output).
// ---------------------------------------------------------------------------

#define NPLANES 16                    // (b,t): b in [0,8), t in {u=0, l=1}
#define PLANE   (34*34*64*32)         // padded plane: 2,367,488 floats
#define HALO_PER_PLANE 270336         // (34*34 - 32*32) * 64 * 32 per-plane halo floats
#define SRC_PER_PLANE 2097152         // 65536 * 32

// Scratch (device-global: allocation-free per harness rules)
__device__ float g_pad[(size_t)NPLANES * PLANE];      // ~151.5 MB
__device__ float g_wt[64 * 9 * 64];                   // [co][tap][ci]
__device__ float g_bpart[NPLANES][64][32];            // per-chunk bias partials

typedef unsigned long long u64t;

__device__ __forceinline__ u64t dup2(float v) {
    u64t r; asm("mov.b64 %0, {%1, %1};" : "=l"(r) : "f"(v)); return r;
}
__device__ __forceinline__ void ffma2(u64t& d, u64t a, u64t b) {
    asm("fma.rn.f32x2 %0, %1, %2, %0;" : "+l"(d) : "l"(a), "l"(b));
}
__device__ __forceinline__ void unpack2(u64t a, float& lo, float& hi) {
    asm("mov.b64 {%0, %1}, %2;" : "=f"(lo), "=f"(hi) : "l"(a));
}

// ---------------------------------------------------------------------------
// 1) Zero only the halo ring of each padded plane (interior overwritten below).
// ---------------------------------------------------------------------------
__global__ void halo_zero_kernel() {
    int j = blockIdx.x * 256 + threadIdx.x;
    if (j >= NPLANES * HALO_PER_PLANE) return;
    int plane = j / HALO_PER_PLANE;
    int r = j % HALO_PER_PLANE;
    int off;
    if (r < 2 * 34 * 2048) {                      // top (wr=0) and bottom (wr=33) rows
        int wr = (r < 34 * 2048) ? 0 : 33;
        int rem = r % (34 * 2048);
        off = wr * (34 * 2048) + rem;
    } else {                                       // left/right columns of rows 1..32
        int q = r - 2 * 34 * 2048;                 // q < 32*2*2048
        int row = q / 4096;
        int s = q % 4096;
        off = (row + 1) * (34 * 2048) + ((s < 2048) ? s : (33 * 2048 + (s - 2048)));
    }
    g_pad[(size_t)plane * PLANE + off] = 0.f;
}

// ---------------------------------------------------------------------------
// 2) Weight transform: g_wt[(co*9 + t)*64 + ci] = kernel[(8-t)*4096 + ci*64 + co]
//    where t = dh*3 + dw, dh,dw in [0,3); tap weight = K[2-dh][2-dw][ci][co].
// ---------------------------------------------------------------------------
__global__ void wtrans_kernel(const float* __restrict__ ker) {
    int j = blockIdx.x * 256 + threadIdx.x;
    if (j >= 64 * 9 * 64) return;
    int ci = j & 63;
    int t  = (j >> 6) % 9;
    int co = j / 576;
    g_wt[j] = ker[(8 - t) * 4096 + ci * 64 + co];
}

// ---------------------------------------------------------------------------
// 3) Pad inputs into g_pad planes + fused deterministic bias partial sums.
//    grid (64 chunks, 16 planes), 256 threads; lane == n everywhere.
// ---------------------------------------------------------------------------
__global__ void __launch_bounds__(256) pad_kernel(
    const float* __restrict__ wu, const float* __restrict__ wl,
    const float* __restrict__ bias)
{
    __shared__ float bs[64];
    __shared__ float red[8][32];
    int plane = blockIdx.y;
    int b = plane >> 1, t = plane & 1;
    const float* src = (t ? wl : wu) + (size_t)b * SRC_PER_PLANE;
    if (threadIdx.x < 64) bs[threadIdx.x] = bias[threadIdx.x];
    __syncthreads();
    int wid = threadIdx.x >> 5, lane = threadIdx.x & 31;
    float* dstp = g_pad + (size_t)plane * PLANE;
    float psum = 0.f;
    int base = blockIdx.x * 32768;
    #pragma unroll 4
    for (int k = 0; k < 128; k++) {
        int e = base + k * 256 + threadIdx.x;
        float v = src[e];
        int f  = e >> 5;           // flat (s*64+co)
        int co = f & 63;
        int s  = f >> 6;
        int wr = (s >> 5) + 1, wc = (s & 31) + 1;
        dstp[((wr * 34 + wc) * 64 + co) * 32 + (e & 31)] = v;
        psum += v * bs[co];
    }
    red[wid][lane] = psum;
    __syncthreads();
    if (wid == 0) {
        float s2 = red[0][lane];
        #pragma unroll
        for (int ww = 1; ww < 8; ww++) s2 += red[ww][lane];
        g_bpart[plane][blockIdx.x][lane] = s2;
    }
}

// ---------------------------------------------------------------------------
// 4) Main conv: FFMA2 (f32x2) hot loop.
//    Block = 8 warps = 2 pixel-groups (2x4 pixels) x 4 ci-groups (8 ci each).
//    Grid  = (64 spatial tiles 4x4, 2 ci-halves, 16 planes).
// ---------------------------------------------------------------------------
__global__ void __launch_bounds__(256, 1) conv_kernel(float* __restrict__ out) {
    const int plane  = blockIdx.z;
    const int b      = plane >> 1, t = plane & 1;
    const int cihalf = blockIdx.y;
    const int tile   = blockIdx.x;
    const int tr = tile >> 3, tc = tile & 7;
    const int wid  = threadIdx.x >> 5, lane = threadIdx.x & 31;
    const int pg   = wid >> 2;          // 0..1  pixel group
    const int cig  = wid & 3;           // 0..3  ci group
    const int r0 = tr * 4 + pg * 2;     // 2 output rows
    const int c0 = tc * 4;              // 4 output cols
    const int cibase = cihalf * 32 + cig * 8;

    const float* pin = g_pad + (size_t)plane * PLANE + (size_t)(r0 * 34 + c0) * 2048 + lane;
    const float* wp0 = g_wt + cibase;

    u64t acc[8][4];
    #pragma unroll
    for (int i = 0; i < 8; i++)
        #pragma unroll
        for (int j = 0; j < 4; j++) acc[i][j] = 0ull;

    for (int co = 0; co < 64; ++co) {
        // load 4x6 window (per-lane n), dup to packed f32x2
        u64t vd[4][6];
        #pragma unroll
        for (int dr = 0; dr < 4; dr++)
            #pragma unroll
            for (int dc = 0; dc < 6; dc++)
                vd[dr][dc] = dup2(__ldg(pin + (dr * 34 + dc) * 2048));

        const float* wp = wp0 + co * 576;
        #pragma unroll
        for (int dh = 0; dh < 3; dh++) {
            #pragma unroll
            for (int dw = 0; dw < 3; dw++) {
                const int tt = dh * 3 + dw;
                // 8 consecutive ci weights -> 4 naturally-packed f32x2 operands
                ulonglong2 wA = *reinterpret_cast<const ulonglong2*>(wp + tt * 64);
                ulonglong2 wB = *reinterpret_cast<const ulonglong2*>(wp + tt * 64 + 4);
                #pragma unroll
                for (int pr = 0; pr < 2; pr++) {
                    #pragma unroll
                    for (int pc = 0; pc < 4; pc++) {
                        u64t a = vd[pr + dh][pc + dw];
                        ffma2(acc[pr * 4 + pc][0], a, wA.x);
                        ffma2(acc[pr * 4 + pc][1], a, wA.y);
                        ffma2(acc[pr * 4 + pc][2], a, wB.x);
                        ffma2(acc[pr * 4 + pc][3], a, wB.y);
                    }
                }
            }
        }
        pin += 32;  // next co (stride 32 floats in padded layout)
    }

    // store: w_u at 0, w_l at 16777472 (after b_u)
    size_t obase = (t ? (size_t)16777472 : (size_t)0) + (size_t)b * 2097152 + lane;
    #pragma unroll
    for (int pr = 0; pr < 2; pr++) {
        #pragma unroll
        for (int pc = 0; pc < 4; pc++) {
            int h = r0 + pr, w = c0 + pc;
            size_t po = obase + (size_t)((h * 32 + w) * 64) * 32;
            #pragma unroll
            for (int cp = 0; cp < 4; cp++) {
                float lo, hi;
                unpack2(acc[pr * 4 + pc][cp], lo, hi);
                int ci = cibase + 2 * cp;
                out[po + (size_t)ci * 32]       = lo;
                out[po + (size_t)(ci + 1) * 32] = hi;
            }
        }
    }
}

// ---------------------------------------------------------------------------
// 5) Bias finalize: sum 64 chunk partials (fixed order -> deterministic),
//    add b_out, write b_u (ofs 16777216) / b_l (ofs 33554688).
// ---------------------------------------------------------------------------
__global__ void bias_fin_kernel(const float* __restrict__ bu,
                                const float* __restrict__ bl,
                                float* __restrict__ out) {
    int plane = threadIdx.x >> 5, lane = threadIdx.x & 31;
    if (plane >= NPLANES) return;
    float s = 0.f;
    #pragma unroll 8
    for (int c = 0; c < 64; c++) s += g_bpart[plane][c][lane];
    int b = plane >> 1, t = plane & 1;
    s += (t ? bl : bu)[b * 32 + lane];
    out[(t ? 33554688 : 16777216) + b * 32 + lane] = s;
}

// ---------------------------------------------------------------------------
// Launch. Inputs (metadata order): x(unused), w_out_u, b_out_u, w_out_l,
// b_out_l, kernel, bias. Output: [w_u | b_u | w_l | b_l] fp32.
// ---------------------------------------------------------------------------
extern "C" void kernel_launch(void* const* d_in, const int* in_sizes, int n_in,
                              void* d_out, int out_size) {
    (void)in_sizes; (void)n_in; (void)out_size;
    const float* w_u  = (const float*)d_in[1];
    const float* b_u  = (const float*)d_in[2];
    const float* w_l  = (const float*)d_in[3];
    const float* b_l  = (const float*)d_in[4];
    const float* ker  = (const float*)d_in[5];
    const float* bias = (const float*)d_in[6];
    float* out = (float*)d_out;

    halo_zero_kernel<<<(NPLANES * HALO_PER_PLANE + 255) / 256, 256>>>();
    wtrans_kernel<<<(64 * 9 * 64 + 255) / 256, 256>>>(ker);
    pad_kernel<<<dim3(64, 16), 256>>>(w_u, w_l, bias);
    conv_kernel<<<dim3(64, 2, 16), 256>>>(out);
    bias_fin_kernel<<<1, 512>>>(b_u, b_l, out);
}

// round 6
// speedup vs baseline: 1.2783x; 1.2783x over previous
#include <cuda_runtime.h>

// ---------------------------------------------------------------------------
// BackwardConv2D: forward SAME 3x3 conv with flipped kernel and Cin/Cout
// swapped, over 512 images (2 tensors x B=8 x N=32) of 32x32x64 fp32.
// lane == n. R5: halved per-warp tile (2x2 px x 8 ci) -> <=128 regs ->
// 2 CTAs/SM -> 4 warps/SMSP to hide load latency (R4 ncu: fma 48.7%,
// issue 29.9%, occ 12.4% with 194 regs / 1 CTA).
// ---------------------------------------------------------------------------

#define NPLANES 16                    // (b,t): b in [0,8), t in {u=0, l=1}
#define PLANE   (34*34*64*32)         // padded plane: 2,367,488 floats
#define HALO_PER_PLANE 270336         // (34*34 - 32*32) * 64 * 32 halo floats
#define SRC_PER_PLANE 2097152         // 65536 * 32

__device__ float g_pad[(size_t)NPLANES * PLANE];      // ~151.5 MB scratch
__device__ float g_wt[64 * 9 * 64];                   // [co][tap][ci]
__device__ float g_bpart[NPLANES][64][32];            // per-chunk bias partials

typedef unsigned long long u64t;

__device__ __forceinline__ u64t dup2(float v) {
    u64t r; asm("mov.b64 %0, {%1, %1};" : "=l"(r) : "f"(v)); return r;
}
__device__ __forceinline__ void ffma2(u64t& d, u64t a, u64t b) {
    asm("fma.rn.f32x2 %0, %1, %2, %0;" : "+l"(d) : "l"(a), "l"(b));
}
__device__ __forceinline__ void unpack2(u64t a, float& lo, float& hi) {
    asm("mov.b64 {%0, %1}, %2;" : "=f"(lo), "=f"(hi) : "l"(a));
}

// ---------------------------------------------------------------------------
// 1) Zero only the halo ring of each padded plane.
// ---------------------------------------------------------------------------
__global__ void halo_zero_kernel() {
    int j = blockIdx.x * 256 + threadIdx.x;
    if (j >= NPLANES * HALO_PER_PLANE) return;
    int plane = j / HALO_PER_PLANE;
    int r = j % HALO_PER_PLANE;
    int off;
    if (r < 2 * 34 * 2048) {
        int wr = (r < 34 * 2048) ? 0 : 33;
        int rem = r % (34 * 2048);
        off = wr * (34 * 2048) + rem;
    } else {
        int q = r - 2 * 34 * 2048;
        int row = q / 4096;
        int s = q % 4096;
        off = (row + 1) * (34 * 2048) + ((s < 2048) ? s : (33 * 2048 + (s - 2048)));
    }
    g_pad[(size_t)plane * PLANE + off] = 0.f;
}

// ---------------------------------------------------------------------------
// 2) Weight transform: g_wt[(co*9 + t)*64 + ci] = kernel[(8-t)*4096 + ci*64 + co]
// ---------------------------------------------------------------------------
__global__ void wtrans_kernel(const float* __restrict__ ker) {
    int j = blockIdx.x * 256 + threadIdx.x;
    if (j >= 64 * 9 * 64) return;
    int ci = j & 63;
    int t  = (j >> 6) % 9;
    int co = j / 576;
    g_wt[j] = ker[(8 - t) * 4096 + ci * 64 + co];
}

// ---------------------------------------------------------------------------
// 3) Pad inputs into g_pad planes + fused deterministic bias partial sums.
// ---------------------------------------------------------------------------
__global__ void __launch_bounds__(256) pad_kernel(
    const float* __restrict__ wu, const float* __restrict__ wl,
    const float* __restrict__ bias)
{
    __shared__ float bs[64];
    __shared__ float red[8][32];
    int plane = blockIdx.y;
    int b = plane >> 1, t = plane & 1;
    const float* src = (t ? wl : wu) + (size_t)b * SRC_PER_PLANE;
    if (threadIdx.x < 64) bs[threadIdx.x] = bias[threadIdx.x];
    __syncthreads();
    int wid = threadIdx.x >> 5, lane = threadIdx.x & 31;
    float* dstp = g_pad + (size_t)plane * PLANE;
    float psum = 0.f;
    int base = blockIdx.x * 32768;
    #pragma unroll 4
    for (int k = 0; k < 128; k++) {
        int e = base + k * 256 + threadIdx.x;
        float v = src[e];
        int f  = e >> 5;
        int co = f & 63;
        int s  = f >> 6;
        int wr = (s >> 5) + 1, wc = (s & 31) + 1;
        dstp[((wr * 34 + wc) * 64 + co) * 32 + (e & 31)] = v;
        psum += v * bs[co];
    }
    red[wid][lane] = psum;
    __syncthreads();
    if (wid == 0) {
        float s2 = red[0][lane];
        #pragma unroll
        for (int ww = 1; ww < 8; ww++) s2 += red[ww][lane];
        g_bpart[plane][blockIdx.x][lane] = s2;
    }
}

// ---------------------------------------------------------------------------
// 4) Main conv: FFMA2 hot loop, 2x2 px x 8 ci per warp, 2 CTAs/SM.
//    Block = 8 warps = 4 pixel-quads (2x2) x 2 ci-groups (8 ci).
//    Grid  = (64 spatial tiles 4x4, 4 ci-quarters, 16 planes).
// ---------------------------------------------------------------------------
__global__ void __launch_bounds__(256, 2) conv_kernel(float* __restrict__ out) {
    const int plane  = blockIdx.z;
    const int b      = plane >> 1, t = plane & 1;
    const int ciq    = blockIdx.y;        // 0..3 (16 ci per block)
    const int tile   = blockIdx.x;
    const int tr = tile >> 3, tc = tile & 7;
    const int wid  = threadIdx.x >> 5, lane = threadIdx.x & 31;
    const int pg   = wid >> 1;            // 0..3 pixel quad in 4x4 tile
    const int cig  = wid & 1;             // 0..1 ci group
    const int r0 = tr * 4 + (pg >> 1) * 2;  // 2 output rows
    const int c0 = tc * 4 + (pg & 1) * 2;   // 2 output cols
    const int cibase = ciq * 16 + cig * 8;

    const float* pin = g_pad + (size_t)plane * PLANE + (size_t)(r0 * 34 + c0) * 2048 + lane;
    const float* wp0 = g_wt + cibase;

    u64t acc[4][4];
    #pragma unroll
    for (int i = 0; i < 4; i++)
        #pragma unroll
        for (int j = 0; j < 4; j++) acc[i][j] = 0ull;

    for (int co = 0; co < 64; ++co) {
        // 4x4 window (per-lane n), dup to packed f32x2
        u64t vd[4][4];
        #pragma unroll
        for (int dr = 0; dr < 4; dr++)
            #pragma unroll
            for (int dc = 0; dc < 4; dc++)
                vd[dr][dc] = dup2(__ldg(pin + (dr * 34 + dc) * 2048));

        const float* wp = wp0 + co * 576;
        #pragma unroll
        for (int dh = 0; dh < 3; dh++) {
            #pragma unroll
            for (int dw = 0; dw < 3; dw++) {
                const int tt = dh * 3 + dw;
                ulonglong2 wA = *reinterpret_cast<const ulonglong2*>(wp + tt * 64);
                ulonglong2 wB = *reinterpret_cast<const ulonglong2*>(wp + tt * 64 + 4);
                #pragma unroll
                for (int pr = 0; pr < 2; pr++) {
                    #pragma unroll
                    for (int pc = 0; pc < 2; pc++) {
                        u64t a = vd[pr + dh][pc + dw];
                        ffma2(acc[pr * 2 + pc][0], a, wA.x);
                        ffma2(acc[pr * 2 + pc][1], a, wA.y);
                        ffma2(acc[pr * 2 + pc][2], a, wB.x);
                        ffma2(acc[pr * 2 + pc][3], a, wB.y);
                    }
                }
            }
        }
        pin += 32;  // next co
    }

    // store: w_u at 0, w_l at 16777472 (after b_u)
    size_t obase = (t ? (size_t)16777472 : (size_t)0) + (size_t)b * 2097152 + lane;
    #pragma unroll
    for (int pr = 0; pr < 2; pr++) {
        #pragma unroll
        for (int pc = 0; pc < 2; pc++) {
            int h = r0 + pr, w = c0 + pc;
            size_t po = obase + (size_t)((h * 32 + w) * 64) * 32;
            #pragma unroll
            for (int cp = 0; cp < 4; cp++) {
                float lo, hi;
                unpack2(acc[pr * 2 + pc][cp], lo, hi);
                int ci = cibase + 2 * cp;
                out[po + (size_t)ci * 32]       = lo;
                out[po + (size_t)(ci + 1) * 32] = hi;
            }
        }
    }
}

// ---------------------------------------------------------------------------
// 5) Bias finalize (fixed-order deterministic sum).
// ---------------------------------------------------------------------------
__global__ void bias_fin_kernel(const float* __restrict__ bu,
                                const float* __restrict__ bl,
                                float* __restrict__ out) {
    int plane = threadIdx.x >> 5, lane = threadIdx.x & 31;
    if (plane >= NPLANES) return;
    float s = 0.f;
    #pragma unroll 8
    for (int c = 0; c < 64; c++) s += g_bpart[plane][c][lane];
    int b = plane >> 1, t = plane & 1;
    s += (t ? bl : bu)[b * 32 + lane];
    out[(t ? 33554688 : 16777216) + b * 32 + lane] = s;
}

// ---------------------------------------------------------------------------
// Launch. Inputs: x(unused), w_out_u, b_out_u, w_out_l, b_out_l, kernel, bias.
// Output: [w_u | b_u | w_l | b_l] fp32.
// ---------------------------------------------------------------------------
extern "C" void kernel_launch(void* const* d_in, const int* in_sizes, int n_in,
                              void* d_out, int out_size) {
    (void)in_sizes; (void)n_in; (void)out_size;
    const float* w_u  = (const float*)d_in[1];
    const float* b_u  = (const float*)d_in[2];
    const float* w_l  = (const float*)d_in[3];
    const float* b_l  = (const float*)d_in[4];
    const float* ker  = (const float*)d_in[5];
    const float* bias = (const float*)d_in[6];
    float* out = (float*)d_out;

    halo_zero_kernel<<<(NPLANES * HALO_PER_PLANE + 255) / 256, 256>>>();
    wtrans_kernel<<<(64 * 9 * 64 + 255) / 256, 256>>>(ker);
    pad_kernel<<<dim3(64, 16), 256>>>(w_u, w_l, bias);
    conv_kernel<<<dim3(64, 4, 16), 256>>>(out);
    bias_fin_kernel<<<1, 512>>>(b_u, b_l, out);
}